// round 17
// baseline (speedup 1.0000x reference)
#include <cuda_runtime.h>
#include <cuda_bf16.h>
#include <cstdint>

#define T_SEQ   80
#define NCLS    80
#define HID     256
#define EMB     8
#define BATCH   8192
#define GATES   1024
#define M_CTA   64
#define NCTA    (BATCH / M_CTA)
#define NTHREADS 512

#define KT1     18      // [biasx][16 x h1 tiles][1 zero pad] ; %3==0
#define KT2     33      // [biasx(zero-x)][16 x h1][16 x h2] ; %3==0

// A columns: [0..15] bias(col0=1)+x(cols 8..15) | [16..271] h1 region0 |
//            [272..527] h1 region1 | [528..783] h2   -> 784 cols
#define A_COLS     784
#define A_STRIDE   792                  // cols; 792/8=99 odd -> conflict-free ldmatrix
#define A_STRIDE_B (A_STRIDE * 2)

#define SM_A        0
#define SM_A_BYTES  (M_CTA * A_STRIDE_B)          // 101376
#define SM_C1       SM_A_BYTES                     // c1: 64x256 fp32 rotated
#define SM_C2       (SM_C1 + M_CTA * HID * 4)      // 166912
#define SM_TOTAL    (SM_C2 + M_CTA * HID * 4)      // 232448 == smem cap

// ---- shared k-tile -> A-column maps (single source of truth for pack+compute) ----
__device__ __forceinline__ int ktcol1(int kt, int h1b) {   // layer1; pad tile -> 0
    return (kt >= 1 && kt < 17) ? h1b + (kt - 1) * 16 : 0;
}
__device__ __forceinline__ int ktcol2(int kt, int h1b) {
    return (kt < 1) ? 0 : (kt < 17 ? h1b + (kt - 1) * 16 : 528 + (kt - 17) * 16);
}

// Packed weights, gate-interleaved fragment-major (proven R10 format), 4 variants:
// v: W1p0, W1p1, W2p0, W2p1. Per-variant uint2 count = KT*4096.
// uint2 idx (within variant) = ((nt*KT + kt)*32 + lane)*4 + gi ; n = gi*256+nt*8+(lane>>2)
#define V1SZ (18 * 4096)
#define V2SZ (33 * 4096)
#define NPK_TOTAL (2 * V1SZ + 2 * V2SZ)            // 417792 uint2
__device__ uint4 g_Wp[NPK_TOTAL / 2];

__global__ void pack_all(const float* __restrict__ W1, const float* __restrict__ b1,
                         const float* __restrict__ W2, const float* __restrict__ b2)
{
    int idx = blockIdx.x * blockDim.x + threadIdx.x;
    if (idx >= NPK_TOTAL) return;
    int layer, p, KT, rem, base;
    if (idx < 2 * V1SZ) { layer = 1; KT = 18; p = idx / V1SZ; rem = idx - p * V1SZ; base = p * V1SZ; }
    else { layer = 2; KT = 33; int j = idx - 2 * V1SZ; p = j / V2SZ; rem = j - p * V2SZ; base = 2 * V1SZ + p * V2SZ; }
    int gi = rem & 3, lane = (rem >> 2) & 31, t = rem >> 7;
    int kt = t % KT, nt = t / KT;
    int th = lane & 3, g = lane >> 2;
    int n  = gi * 256 + nt * 8 + g;
    int h1b = (layer == 1) ? 16 + 256 * (1 - p) : 16 + 256 * p;
    int ktc = (layer == 1) ? ktcol1(kt, h1b) : ktcol2(kt, h1b);
    float v[4];
#pragma unroll
    for (int i = 0; i < 4; i++) {
        int c = ktc + th * 2 + ((i >> 1) * 8) + (i & 1);
        float val = 0.f;
        if (!(layer == 1 && kt == 17)) {           // L1 pad tile = exact zeros
            if (layer == 1) {
                if (c == 0)                         val = b1[n];
                else if (c >= 8 && c < 16)          val = W1[(size_t)(c - 8) * GATES + n];
                else if (c >= h1b && c < h1b + 256) val = W1[(size_t)(8 + c - h1b) * GATES + n];
            } else {
                if (c == 0)                         val = b2[n];
                else if (c >= h1b && c < h1b + 256) val = W2[(size_t)(c - h1b) * GATES + n];
                else if (c >= 528)                  val = W2[(size_t)(256 + c - 528) * GATES + n];
            }
        }
        v[i] = val;
    }
    __nv_bfloat162 p0 = __floats2bfloat162_rn(v[0], v[1]);
    __nv_bfloat162 p1 = __floats2bfloat162_rn(v[2], v[3]);
    uint2 o;
    o.x = *reinterpret_cast<uint32_t*>(&p0);
    o.y = *reinterpret_cast<uint32_t*>(&p1);
    reinterpret_cast<uint2*>(g_Wp)[base + rem] = o;
}

__device__ __forceinline__ float fast_tanh(float x) {
    float y; asm("tanh.approx.f32 %0, %1;" : "=f"(y) : "f"(x)); return y;
}
__device__ __forceinline__ float fast_sigmoid(float x) {
    return fmaf(fast_tanh(0.5f * x), 0.5f, 0.5f);
}
__device__ __forceinline__ void ldsm4(uint32_t a[4], uint32_t addr) {
    asm volatile("ldmatrix.sync.aligned.m8n8.x4.shared.b16 {%0,%1,%2,%3}, [%4];\n"
                 : "=r"(a[0]), "=r"(a[1]), "=r"(a[2]), "=r"(a[3]) : "r"(addr));
}
__device__ __forceinline__ void mma_bf16(float c[4], const uint32_t a[4], uint32_t b0, uint32_t b1) {
    asm volatile("mma.sync.aligned.m16n8k16.row.col.f32.bf16.bf16.f32 "
                 "{%0,%1,%2,%3}, {%4,%5,%6,%7}, {%8,%9}, {%0,%1,%2,%3};\n"
                 : "+f"(c[0]), "+f"(c[1]), "+f"(c[2]), "+f"(c[3])
                 : "r"(a[0]), "r"(a[1]), "r"(a[2]), "r"(a[3]), "r"(b0), "r"(b1));
}

// One k-tile: 4 M-fragments x 4 gates, af ping-pong prefetch (R16-proven).
__device__ __forceinline__ void sub_mts(float (&acc)[4][4][4], uint32_t (&af)[2][4],
                                        const uint4& Sa, const uint4& Sb,
                                        uint32_t col_addr, uint32_t next_addr, bool pref_next)
{
#pragma unroll
    for (int mt = 0; mt < 4; mt++) {
        const int cur = mt & 1, nxt = cur ^ 1;
        if (mt < 3)
            ldsm4(af[nxt], col_addr + (uint32_t)((mt + 1) * (16 * A_STRIDE_B)));
        else if (pref_next)
            ldsm4(af[nxt], next_addr);
        mma_bf16(acc[mt][0], af[cur], Sa.x, Sa.y);
        mma_bf16(acc[mt][1], af[cur], Sa.z, Sa.w);
        mma_bf16(acc[mt][2], af[cur], Sb.x, Sb.y);
        mma_bf16(acc[mt][3], af[cur], Sb.z, Sb.w);
    }
}

// One LSTM layer, 16 warps x (Mw=64, Nw=32) x 2 waves.
// L1: h1(t) written directly to parity region p (unread this phase).
// L2: h2(t) held in regs (committed after the read-drain barrier).
template<int KT, int LAYER>
__device__ __forceinline__ void lstm_layer(
    uint32_t sbase, const uint4* __restrict__ Wp, char* __restrict__ smem,
    int p, uint32_t (&hold)[2][4][2], int wn, int lane)
{
    static_assert(KT % 3 == 0, "KT must be divisible by 3");
    const int th = lane & 3, g = lane >> 2;
    const uint32_t a_base = sbase +
        (uint32_t)((lane & 15) * A_STRIDE_B + ((lane >> 4) << 4));
    const int h1b = (LAYER == 1) ? 16 + 256 * (1 - p) : 16 + 256 * p;
    float* cbuf = (float*)(smem + ((LAYER == 1) ? SM_C1 : SM_C2));
    const int hwbase = 16 + 256 * p;     // L1 h-write region

#pragma unroll
    for (int wave = 0; wave < 2; wave++) {
        const int hblk = wave * 16 + wn;
        float acc[4][4][4];
#pragma unroll
        for (int mt = 0; mt < 4; mt++)
#pragma unroll
            for (int gi = 0; gi < 4; gi++)
#pragma unroll
                for (int i = 0; i < 4; i++) acc[mt][gi][i] = 0.f;

        const uint4* bb = Wp + ((size_t)(hblk * KT) * 32 + lane) * 2;
        uint4 A0 = __ldg(bb + 0),   A1 = __ldg(bb + 1);
        uint4 B0 = __ldg(bb + 64),  B1 = __ldg(bb + 65);
        uint4 C0 = __ldg(bb + 128), C1 = __ldg(bb + 129);

        auto KC = [&](int k) -> uint32_t {
            int c = (LAYER == 1) ? ktcol1(k, h1b) : ktcol2(k, h1b);
            return a_base + (uint32_t)(c * 2);
        };

        uint32_t af[2][4];
        uint32_t ad0 = KC(0), ad1 = KC(1), ad2 = KC(2);
        ldsm4(af[0], ad0);

#pragma unroll 1
        for (int kt = 0; kt < KT; kt += 3) {
            uint32_t ad3 = KC(kt + 3), ad4 = KC(kt + 4), ad5 = KC(kt + 5);
            sub_mts(acc, af, A0, A1, ad0, ad1, true);
            if (kt + 3 < KT) { A0 = __ldg(bb + 192); A1 = __ldg(bb + 193); }
            sub_mts(acc, af, B0, B1, ad1, ad2, true);
            if (kt + 4 < KT) { B0 = __ldg(bb + 256); B1 = __ldg(bb + 257); }
            sub_mts(acc, af, C0, C1, ad2, ad3, kt + 3 < KT);
            if (kt + 5 < KT) { C0 = __ldg(bb + 320); C1 = __ldg(bb + 321); }
            bb += 192; ad0 = ad3; ad1 = ad4; ad2 = ad5;
        }

        // elementwise (i=0,j=1,f=2,o=3); rows mt*16+g+rb*8, cols hblk*8+th*2(+q)
        const int colc = hblk * 8 + th * 2;
#pragma unroll
        for (int mt = 0; mt < 4; mt++)
#pragma unroll
            for (int rb = 0; rb < 2; rb++) {
                const int r = mt * 16 + g + rb * 8;
                // rotated c layout: word = r*256 + ((col + 2r) & 255)
                const uint32_t coff = (uint32_t)(colc + 2 * r) & 255u;
                float2* cc = reinterpret_cast<float2*>((char*)cbuf + (r * 256 + coff) * 4);
                float2 cold = *cc;
                float co[2] = { cold.x, cold.y };
                float nc[2], hv[2];
#pragma unroll
                for (int q = 0; q < 2; q++) {
                    const int ci = rb * 2 + q;
                    nc[q] = co[q] * fast_sigmoid(acc[mt][2][ci] + 1.0f)
                          + fast_sigmoid(acc[mt][0][ci]) * fast_tanh(acc[mt][1][ci]);
                    hv[q] = fast_tanh(nc[q]) * fast_sigmoid(acc[mt][3][ci]);
                }
                *cc = make_float2(nc[0], nc[1]);
                __nv_bfloat162 hb = __floats2bfloat162_rn(hv[0], hv[1]);
                uint32_t packed = *reinterpret_cast<uint32_t*>(&hb);
                if (LAYER == 1)
                    *reinterpret_cast<uint32_t*>(smem + r * A_STRIDE_B + (hwbase + colc) * 2) = packed;
                else
                    hold[wave][mt][rb] = packed;
            }
    }
}

__device__ __forceinline__ void commit_h2(char* smem, const uint32_t (&hold)[2][4][2],
                                          int wn, int lane)
{
    const int th = lane & 3, g = lane >> 2;
#pragma unroll
    for (int wave = 0; wave < 2; wave++) {
        const int col = 528 + (wave * 16 + wn) * 8 + th * 2;
#pragma unroll
        for (int mt = 0; mt < 4; mt++)
#pragma unroll
            for (int rb = 0; rb < 2; rb++) {
                const int r = mt * 16 + g + rb * 8;
                *reinterpret_cast<uint32_t*>(smem + r * A_STRIDE_B + col * 2) = hold[wave][mt][rb];
            }
    }
}

__device__ __forceinline__ void write_x(char* smem, const float* __restrict__ embedding,
                                        const int* __restrict__ features,
                                        int rowbase, int t, int tid)
{
    if (tid < M_CTA) {
        int f = features[(rowbase + tid) * T_SEQ + t];
        const float4* e = reinterpret_cast<const float4*>(embedding + f * EMB);
        float4 e0 = __ldg(e), e1 = __ldg(e + 1);
        uint32_t* dst = reinterpret_cast<uint32_t*>(smem + tid * A_STRIDE_B + 16);
        __nv_bfloat162 q0 = __floats2bfloat162_rn(e0.x, e0.y);
        __nv_bfloat162 q1 = __floats2bfloat162_rn(e0.z, e0.w);
        __nv_bfloat162 q2 = __floats2bfloat162_rn(e1.x, e1.y);
        __nv_bfloat162 q3 = __floats2bfloat162_rn(e1.z, e1.w);
        dst[0] = *reinterpret_cast<uint32_t*>(&q0);
        dst[1] = *reinterpret_cast<uint32_t*>(&q1);
        dst[2] = *reinterpret_cast<uint32_t*>(&q2);
        dst[3] = *reinterpret_cast<uint32_t*>(&q3);
    }
}

__global__ void __launch_bounds__(NTHREADS, 1) lstm_kernel(
    const int* __restrict__ features, const int* __restrict__ labels,
    const float* __restrict__ embedding,
    const float* __restrict__ Wd, const float* __restrict__ bd,
    float* __restrict__ out)
{
    extern __shared__ char smem[];
    const int tid = threadIdx.x;
    const int wn = tid >> 5, lane = tid & 31;
    const int rowbase = blockIdx.x * M_CTA;

    for (int i = tid; i < SM_TOTAL / 4; i += NTHREADS)
        ((uint32_t*)smem)[i] = 0u;
    __syncthreads();
    if (tid < M_CTA)   // bias column 0
        *reinterpret_cast<__nv_bfloat16*>(smem + tid * A_STRIDE_B) = __float2bfloat16(1.0f);
    write_x(smem, embedding, features, rowbase, 0, tid);
    __syncthreads();

    const uint32_t sbase = (uint32_t)__cvta_generic_to_shared(smem);
    uint32_t hold[2][4][2];

    const uint4* W1base[2] = { g_Wp,              g_Wp + V1SZ / 2 };
    const uint4* W2base[2] = { g_Wp + V1SZ,       g_Wp + V1SZ + V2SZ / 2 };

    for (int t = 0; t < T_SEQ; t++) {
        const int p = t & 1;
        lstm_layer<KT1, 1>(sbase, W1base[p], smem, p, hold, wn, lane);
        __syncthreads();                                   // h1(t) visible
        lstm_layer<KT2, 2>(sbase, W2base[p], smem, p, hold, wn, lane);
        if (t + 1 < T_SEQ) write_x(smem, embedding, features, rowbase, t + 1, tid);
        __syncthreads();                                   // all L2 A-reads done (+x visible)
        commit_h2(smem, hold, wn, lane);                   // races only unread h2 cols
    }
    __syncthreads();

    // dense + log-softmax (logits scratch aliases dead c1 region)
    float* logits = (float*)(smem + SM_C1);
    for (int item = tid; item < M_CTA * NCLS; item += NTHREADS) {
        int row = item / NCLS, cls = item - row * NCLS;
        const __nv_bfloat16* h2p = (const __nv_bfloat16*)(smem + row * A_STRIDE_B + 528 * 2);
        float acc = __ldg(&bd[cls]);
#pragma unroll 8
        for (int k = 0; k < HID; k++)
            acc += __bfloat162float(h2p[k]) * __ldg(&Wd[k * NCLS + cls]);
        logits[item] = acc;
    }
    __syncthreads();
    if (tid < M_CTA) {
        const float* lr = logits + tid * NCLS;
        float mx = -1e30f;
        for (int c = 0; c < NCLS; c++) mx = fmaxf(mx, lr[c]);
        float s = 0.f;
        for (int c = 0; c < NCLS; c++) s += __expf(lr[c] - mx);
        int lab = labels[rowbase + tid];
        out[rowbase + tid] = mx + __logf(s) - lr[lab];
    }
}

extern "C" void kernel_launch(void* const* d_in, const int* in_sizes, int n_in,
                              void* d_out, int out_size)
{
    const int*   features  = (const int*)  d_in[0];
    const int*   labels    = (const int*)  d_in[1];
    const float* embedding = (const float*)d_in[2];
    const float* W1        = (const float*)d_in[3];
    const float* b1        = (const float*)d_in[4];
    const float* W2        = (const float*)d_in[5];
    const float* b2        = (const float*)d_in[6];
    const float* Wd        = (const float*)d_in[7];
    const float* bd        = (const float*)d_in[8];
    float* out = (float*)d_out;

    pack_all<<<(NPK_TOTAL + 255) / 256, 256>>>(W1, b1, W2, b2);

    cudaFuncSetAttribute(lstm_kernel, cudaFuncAttributeMaxDynamicSharedMemorySize, SM_TOTAL);
    lstm_kernel<<<NCTA, NTHREADS, SM_TOTAL>>>(features, labels, embedding, Wd, bd, out);
}